// round 3
// baseline (speedup 1.0000x reference)
#include <cuda_runtime.h>

#define HW   4096
#define CCH  64
#define BB   4
#define KK   8

// Scratch (allocation-free rule: __device__ globals)
__device__ float g_f[BB * HW * KK];      // [b][n][k]  (n-major, 8 contiguous)
__device__ float g_g[BB * HW * KK];      // [b][n][k]
__device__ float g_h[BB * CCH * HW];     // [b][c][n]
__device__ float g_part[BB * 4 * HW];    // partial denom sums, 4 m-quarters
__device__ float g_rden[BB * HW];        // 1/denom per (b,n)

// ---------------------------------------------------------------------------
// Kernel A: f = Wf@x+bf, g = Wg@x+bg, h = Wh@x+bh   (1x1 convs over channels)
// grid (32 n-chunks, 4 b), 256 threads. Thread handles one n (of 128) and
// half the outputs: half0 -> h rows 0..31 + f[0..7]; half1 -> h 32..63 + g.
// ---------------------------------------------------------------------------
__global__ __launch_bounds__(256) void kA(
    const float* __restrict__ x,
    const float* __restrict__ Wf, const float* __restrict__ bf,
    const float* __restrict__ Wg, const float* __restrict__ bg,
    const float* __restrict__ Wh, const float* __restrict__ bh)
{
    __shared__ float xs[64 * 128];
    const int t  = threadIdx.x;
    const int b  = blockIdx.y;
    const int n0 = blockIdx.x * 128;

    // Load x tile [64 c][128 n], coalesced
    #pragma unroll
    for (int r = 0; r < 32; r++) {
        int lin = r * 256 + t;
        int c = lin >> 7, nn = lin & 127;
        xs[lin] = x[((b * 64 + c) << 12) + n0 + nn];
    }
    __syncthreads();

    const int n = t & 127, half = t >> 7;
    const int rowbase = half * 32;
    const float* Wfg = half ? Wg : Wf;
    const float* bfg = half ? bg : bf;

    float acch[32], accfg[8];
    #pragma unroll
    for (int o = 0; o < 32; o++) acch[o] = bh[rowbase + o];
    #pragma unroll
    for (int k = 0; k < 8; k++)  accfg[k] = bfg[k];

    #pragma unroll
    for (int c0 = 0; c0 < 64; c0 += 8) {
        float xv[8];
        #pragma unroll
        for (int j = 0; j < 8; j++) xv[j] = xs[(c0 + j) * 128 + n];

        #pragma unroll
        for (int o = 0; o < 32; o++) {
            const float4* w = (const float4*)(Wh + (rowbase + o) * 64 + c0);
            float4 w0 = w[0], w1 = w[1];
            acch[o] += w0.x * xv[0] + w0.y * xv[1] + w0.z * xv[2] + w0.w * xv[3]
                     + w1.x * xv[4] + w1.y * xv[5] + w1.z * xv[6] + w1.w * xv[7];
        }
        #pragma unroll
        for (int k = 0; k < 8; k++) {
            const float4* w = (const float4*)(Wfg + k * 64 + c0);
            float4 w0 = w[0], w1 = w[1];
            accfg[k] += w0.x * xv[0] + w0.y * xv[1] + w0.z * xv[2] + w0.w * xv[3]
                      + w1.x * xv[4] + w1.y * xv[5] + w1.z * xv[6] + w1.w * xv[7];
        }
    }

    const int ng = n0 + n;
    #pragma unroll
    for (int o = 0; o < 32; o++)
        g_h[((b * 64 + rowbase + o) << 12) + ng] = acch[o];

    float* dst = (half ? g_g : g_f) + (b * HW + ng) * 8;
    *(float4*)(dst)     = make_float4(accfg[0], accfg[1], accfg[2], accfg[3]);
    *(float4*)(dst + 4) = make_float4(accfg[4], accfg[5], accfg[6], accfg[7]);
}

// ---------------------------------------------------------------------------
// Kernel B1: partial denominators. denom[b][n] = sum_m exp(f_m . g_n)
// grid (16 n-chunks of 256, 4 m-quarters of 1024, 4 b), 256 threads.
// ---------------------------------------------------------------------------
__global__ __launch_bounds__(256) void kB1()
{
    __shared__ float fs[128 * 8];
    const int t  = threadIdx.x;
    const int b  = blockIdx.z;
    const int mq = blockIdx.y;
    const int n  = blockIdx.x * 256 + t;

    const float4* gp = (const float4*)&g_g[(b * HW + n) * 8];
    const float4 gv0 = gp[0], gv1 = gp[1];

    float acc0 = 0.f, acc1 = 0.f;
    const int mend = mq * 1024 + 1024;
    for (int m0 = mq * 1024; m0 < mend; m0 += 128) {
        ((float4*)fs)[t] = ((const float4*)&g_f[(b * HW + m0) * 8])[t];
        __syncthreads();
        #pragma unroll 8
        for (int mm = 0; mm < 128; mm += 2) {
            float4 f0 = *(float4*)&fs[mm * 8];
            float4 f1 = *(float4*)&fs[mm * 8 + 4];
            float s0 = f0.x * gv0.x + f0.y * gv0.y + f0.z * gv0.z + f0.w * gv0.w
                     + f1.x * gv1.x + f1.y * gv1.y + f1.z * gv1.z + f1.w * gv1.w;
            acc0 += __expf(s0);
            float4 h0 = *(float4*)&fs[(mm + 1) * 8];
            float4 h1 = *(float4*)&fs[(mm + 1) * 8 + 4];
            float s1 = h0.x * gv0.x + h0.y * gv0.y + h0.z * gv0.z + h0.w * gv0.w
                     + h1.x * gv1.x + h1.y * gv1.y + h1.z * gv1.z + h1.w * gv1.w;
            acc1 += __expf(s1);
        }
        __syncthreads();
    }
    g_part[(b * 4 + mq) * HW + n] = acc0 + acc1;
}

// Kernel B2: reduce quarters, reciprocal.
__global__ __launch_bounds__(256) void kB2()
{
    int i = blockIdx.x * 256 + threadIdx.x;      // 0..16383 = b*4096+n
    int b = i >> 12, n = i & 4095;
    float s = g_part[(b * 4 + 0) * HW + n] + g_part[(b * 4 + 1) * HW + n]
            + g_part[(b * 4 + 2) * HW + n] + g_part[(b * 4 + 3) * HW + n];
    g_rden[i] = 1.0f / s;
}

// ---------------------------------------------------------------------------
// Kernel C: O[c,m] = sum_{n>=m} exp(f_m.g_n) * h[c,n]/denom[n]; y = g*O + x.
// One block per (b, 64-row m-tile); loops n-tiles of 64 from the diagonal.
// Phase 1: P tile in smem (exp). Phase 2: 4x4 register-blocked fp32 GEMM.
// Task permutation pairs long tiles with short ones across occupancy slots.
// ---------------------------------------------------------------------------
__global__ __launch_bounds__(256) void kC(
    const float* __restrict__ x,
    const float* __restrict__ gamma,
    float* __restrict__ out)
{
    __shared__ float fs[64 * 8];
    __shared__ float gs[64 * 8];
    __shared__ float Pt[64 * 68];   // [n][m], padded
    __shared__ float Vt[64 * 68];   // [n][c], padded

    const int tid = threadIdx.x;
    const int bid = blockIdx.x;
    const int tsk = (bid < 128) ? bid : (383 - bid);   // descending-cost order
    const int mt = tsk >> 2, b = tsk & 3;
    const int m_base = mt * 64;

    // f tile [64 m][8], loaded once
    ((float2*)fs)[tid] = ((const float2*)&g_f[(b * HW + m_base) * 8])[tid];

    float acc[4][4];
    #pragma unroll
    for (int i = 0; i < 4; i++)
        #pragma unroll
        for (int j = 0; j < 4; j++) acc[i][j] = 0.f;

    const int tx = tid & 15, ty = tid >> 4;
    const int tc = tx * 4, tm = ty * 4;
    const int nloc = tid >> 2, mgrp = tid & 3;

    for (int n0 = m_base; n0 < HW; n0 += 64) {
        // g tile [64 n][8]
        ((float2*)gs)[tid] = ((const float2*)&g_g[(b * HW + n0) * 8])[tid];
        // V' tile: Vt[n][c] = h[b][c][n0+n] * rden[n0+n]  (coalesced over n)
        #pragma unroll
        for (int r = 0; r < 16; r++) {
            int lin = r * 256 + tid;
            int c = lin >> 6, nn = lin & 63;
            Vt[nn * 68 + c] = g_h[((b * 64 + c) << 12) + n0 + nn]
                            * g_rden[b * HW + n0 + nn];
        }
        __syncthreads();

        // Phase 1: P[n][m] = exp(f_m . g_n), masked to n >= m (only diag tile)
        {
            float4 gv0 = *(float4*)&gs[nloc * 8];
            float4 gv1 = *(float4*)&gs[nloc * 8 + 4];
            int ng = n0 + nloc;
            #pragma unroll
            for (int i = 0; i < 16; i++) {
                int mloc = mgrp * 16 + i;
                float4 f0 = *(float4*)&fs[mloc * 8];
                float4 f1 = *(float4*)&fs[mloc * 8 + 4];
                float s = f0.x * gv0.x + f0.y * gv0.y + f0.z * gv0.z + f0.w * gv0.w
                        + f1.x * gv1.x + f1.y * gv1.y + f1.z * gv1.z + f1.w * gv1.w;
                float p = __expf(s);
                if (ng < m_base + mloc) p = 0.f;
                Pt[nloc * 68 + mloc] = p;
            }
        }
        __syncthreads();

        // Phase 2: acc[m][c] += sum_n P[n][m] * V'[n][c]
        #pragma unroll 8
        for (int nn = 0; nn < 64; nn++) {
            float4 pv = *(float4*)&Pt[nn * 68 + tm];
            float4 vv = *(float4*)&Vt[nn * 68 + tc];
            acc[0][0] += pv.x * vv.x; acc[0][1] += pv.x * vv.y;
            acc[0][2] += pv.x * vv.z; acc[0][3] += pv.x * vv.w;
            acc[1][0] += pv.y * vv.x; acc[1][1] += pv.y * vv.y;
            acc[1][2] += pv.y * vv.z; acc[1][3] += pv.y * vv.w;
            acc[2][0] += pv.z * vv.x; acc[2][1] += pv.z * vv.y;
            acc[2][2] += pv.z * vv.z; acc[2][3] += pv.z * vv.w;
            acc[3][0] += pv.w * vv.x; acc[3][1] += pv.w * vv.y;
            acc[3][2] += pv.w * vv.z; acc[3][3] += pv.w * vv.w;
        }
        __syncthreads();
    }

    const float gm = gamma[0];
    #pragma unroll
    for (int i = 0; i < 4; i++) {
        #pragma unroll
        for (int j = 0; j < 4; j++) {
            int m = m_base + tm + i;
            int c = tc + j;
            int idx = ((b * 64 + c) << 12) + m;
            out[idx] = gm * acc[i][j] + x[idx];
        }
    }
}

// ---------------------------------------------------------------------------
extern "C" void kernel_launch(void* const* d_in, const int* in_sizes, int n_in,
                              void* d_out, int out_size)
{
    const float* x     = (const float*)d_in[0];
    const float* Wf    = (const float*)d_in[1];
    const float* bf    = (const float*)d_in[2];
    const float* Wg    = (const float*)d_in[3];
    const float* bg    = (const float*)d_in[4];
    const float* Wh    = (const float*)d_in[5];
    const float* bh    = (const float*)d_in[6];
    const float* gamma = (const float*)d_in[7];
    float* out = (float*)d_out;

    kA<<<dim3(32, 4), 256>>>(x, Wf, bf, Wg, bg, Wh, bh);
    kB1<<<dim3(16, 4, 4), 256>>>();
    kB2<<<64, 256>>>();
    kC<<<256, 256>>>(x, gamma, out);
}

// round 5
// speedup vs baseline: 1.4562x; 1.4562x over previous
#include <cuda_runtime.h>

#define HW   4096
#define CCH  64
#define BB   4
#define KK   8

// Scratch (allocation-free rule: __device__ globals)
__device__ float g_f[BB * HW * KK];      // [b][n][k]
__device__ float g_g[BB * HW * KK];      // [b][n][k]
__device__ float g_h[BB * CCH * HW];     // [b][c][n]
__device__ float g_part[BB * 4 * HW];    // partial denom sums
__device__ float g_rden[BB * HW];        // 1/denom
__device__ float g_O[BB * CCH * HW];     // attention output accumulator

// ---------------------------------------------------------------------------
// Zero the O accumulator. g_O = 1,048,576 floats = 262,144 float4
//  -> grid 1024 x 256 threads x 1 float4.
// ---------------------------------------------------------------------------
__global__ __launch_bounds__(256) void kZ()
{
    ((float4*)g_O)[blockIdx.x * 256 + threadIdx.x] = make_float4(0.f, 0.f, 0.f, 0.f);
}

// ---------------------------------------------------------------------------
// Kernel A: f = Wf@x+bf, g = Wg@x+bg, h = Wh@x+bh (1x1 convs)
// ---------------------------------------------------------------------------
__global__ __launch_bounds__(256) void kA(
    const float* __restrict__ x,
    const float* __restrict__ Wf, const float* __restrict__ bf,
    const float* __restrict__ Wg, const float* __restrict__ bg,
    const float* __restrict__ Wh, const float* __restrict__ bh)
{
    __shared__ float xs[64 * 128];
    const int t  = threadIdx.x;
    const int b  = blockIdx.y;
    const int n0 = blockIdx.x * 128;

    #pragma unroll
    for (int r = 0; r < 32; r++) {
        int lin = r * 256 + t;
        int c = lin >> 7, nn = lin & 127;
        xs[lin] = x[((b * 64 + c) << 12) + n0 + nn];
    }
    __syncthreads();

    const int n = t & 127, half = t >> 7;
    const int rowbase = half * 32;
    const float* Wfg = half ? Wg : Wf;
    const float* bfg = half ? bg : bf;

    float acch[32], accfg[8];
    #pragma unroll
    for (int o = 0; o < 32; o++) acch[o] = bh[rowbase + o];
    #pragma unroll
    for (int k = 0; k < 8; k++)  accfg[k] = bfg[k];

    #pragma unroll
    for (int c0 = 0; c0 < 64; c0 += 8) {
        float xv[8];
        #pragma unroll
        for (int j = 0; j < 8; j++) xv[j] = xs[(c0 + j) * 128 + n];

        #pragma unroll
        for (int o = 0; o < 32; o++) {
            const float4* w = (const float4*)(Wh + (rowbase + o) * 64 + c0);
            float4 w0 = w[0], w1 = w[1];
            acch[o] += w0.x * xv[0] + w0.y * xv[1] + w0.z * xv[2] + w0.w * xv[3]
                     + w1.x * xv[4] + w1.y * xv[5] + w1.z * xv[6] + w1.w * xv[7];
        }
        #pragma unroll
        for (int k = 0; k < 8; k++) {
            const float4* w = (const float4*)(Wfg + k * 64 + c0);
            float4 w0 = w[0], w1 = w[1];
            accfg[k] += w0.x * xv[0] + w0.y * xv[1] + w0.z * xv[2] + w0.w * xv[3]
                      + w1.x * xv[4] + w1.y * xv[5] + w1.z * xv[6] + w1.w * xv[7];
        }
    }

    const int ng = n0 + n;
    #pragma unroll
    for (int o = 0; o < 32; o++)
        g_h[((b * 64 + rowbase + o) << 12) + ng] = acch[o];

    float* dst = (half ? g_g : g_f) + (b * HW + ng) * 8;
    *(float4*)(dst)     = make_float4(accfg[0], accfg[1], accfg[2], accfg[3]);
    *(float4*)(dst + 4) = make_float4(accfg[4], accfg[5], accfg[6], accfg[7]);
}

// ---------------------------------------------------------------------------
// Kernel B1: partial denominators, 2 n per thread (16 FMA per 32B LDS).
// grid (8 n-chunks of 256, 4 m-quarters, 4 b), 256 threads.
// ---------------------------------------------------------------------------
__global__ __launch_bounds__(256) void kB1()
{
    __shared__ float fs[128 * 8];
    const int t  = threadIdx.x;
    const int b  = blockIdx.z;
    const int mq = blockIdx.y;
    const int na = blockIdx.x * 256 + t;
    const int nb = na + 2048;

    const float4* gpa = (const float4*)&g_g[(b * HW + na) * 8];
    const float4 ga0 = gpa[0], ga1 = gpa[1];
    const float4* gpb = (const float4*)&g_g[(b * HW + nb) * 8];
    const float4 gb0 = gpb[0], gb1 = gpb[1];

    float acca = 0.f, accb = 0.f;
    const int mend = mq * 1024 + 1024;
    for (int m0 = mq * 1024; m0 < mend; m0 += 128) {
        ((float4*)fs)[t] = ((const float4*)&g_f[(b * HW + m0) * 8])[t];
        __syncthreads();
        #pragma unroll 8
        for (int mm = 0; mm < 128; mm++) {
            float4 f0 = *(float4*)&fs[mm * 8];
            float4 f1 = *(float4*)&fs[mm * 8 + 4];
            float sa = f0.x * ga0.x + f0.y * ga0.y + f0.z * ga0.z + f0.w * ga0.w
                     + f1.x * ga1.x + f1.y * ga1.y + f1.z * ga1.z + f1.w * ga1.w;
            float sb = f0.x * gb0.x + f0.y * gb0.y + f0.z * gb0.z + f0.w * gb0.w
                     + f1.x * gb1.x + f1.y * gb1.y + f1.z * gb1.z + f1.w * gb1.w;
            acca += __expf(sa);
            accb += __expf(sb);
        }
        __syncthreads();
    }
    g_part[(b * 4 + mq) * HW + na] = acca;
    g_part[(b * 4 + mq) * HW + nb] = accb;
}

__global__ __launch_bounds__(256) void kB2()
{
    int i = blockIdx.x * 256 + threadIdx.x;
    int b = i >> 12, n = i & 4095;
    float s = g_part[(b * 4 + 0) * HW + n] + g_part[(b * 4 + 1) * HW + n]
            + g_part[(b * 4 + 2) * HW + n] + g_part[(b * 4 + 3) * HW + n];
    g_rden[i] = 1.0f / s;
}

// ---------------------------------------------------------------------------
// Kernel C: masked attention GEMM, n-chunked with atomic reduction.
// Tasks: for each (b, mt of 64 m-rows), n range [mt*64, 4096) split into
// chunks of 16 n-tiles (1024 cols). 160 tasks/batch * 4 = 640 blocks.
// 128 threads; thread tile 8m x 4c; P tile recomputed in smem per n-tile.
// ---------------------------------------------------------------------------
__global__ __launch_bounds__(128) void kC()
{
    __shared__ float fs[64 * 8];
    __shared__ float gs[64 * 8];
    __shared__ float Pt[64 * 68];   // [n][m], pad 4
    __shared__ float Vt[64 * 68];   // [n][c], pad 4

    const int tid = threadIdx.x;
    const int bid = blockIdx.x;
    const int b = bid & 3;
    int t = bid >> 2;                     // task 0..159

    // task -> (mt, chunk)
    int mt = 0;
    for (;;) {
        int ch = (64 - mt + 15) >> 4;
        if (t < ch) break;
        t -= ch; mt++;
    }
    const int m_base = mt * 64;
    const int nt_begin = mt + t * 16;
    const int nt_end = (nt_begin + 16 < 64) ? nt_begin + 16 : 64;

    // f tile [64 m][8], once per block (512 floats / 128 thr = 1 float4)
    ((float4*)fs)[tid] = ((const float4*)&g_f[(b * HW + m_base) * 8])[tid];

    float acc[8][4];
    #pragma unroll
    for (int i = 0; i < 8; i++)
        #pragma unroll
        for (int j = 0; j < 4; j++) acc[i][j] = 0.f;

    const int tc  = (tid & 15) * 4;   // c base (phase 2)
    const int tm  = (tid >> 4) * 8;   // m base (phase 2)
    const int ng0 = tid & 15;         // n lane (phase 1), n = ng0 + 16j
    const int mg0 = (tid >> 4) * 8;   // m base (phase 1)

    for (int nt = nt_begin; nt < nt_end; nt++) {
        const int n0 = nt * 64;
        ((float4*)gs)[tid] = ((const float4*)&g_g[(b * HW + n0) * 8])[tid];

        // V' tile: Vt[n][c] = h[b][c][n0+n] * rden[n0+n]
        #pragma unroll
        for (int r = 0; r < 32; r++) {
            int lin = r * 128 + tid;
            int c = lin >> 6, nn = lin & 63;
            Vt[nn * 68 + c] = g_h[((b * 64 + c) << 12) + n0 + nn]
                            * g_rden[b * HW + n0 + nn];
        }
        __syncthreads();

        // Phase 1: P[n][m] = exp(f_m . g_n); diagonal tile masked to n >= m
        const bool diag = (nt == mt);
        #pragma unroll
        for (int j = 0; j < 4; j++) {
            const int nloc = ng0 + 16 * j;
            float4 gv0 = *(float4*)&gs[nloc * 8];
            float4 gv1 = *(float4*)&gs[nloc * 8 + 4];
            float pv[8];
            #pragma unroll
            for (int i = 0; i < 8; i++) {
                const int mloc = mg0 + i;
                float4 f0 = *(float4*)&fs[mloc * 8];
                float4 f1 = *(float4*)&fs[mloc * 8 + 4];
                float s = f0.x * gv0.x + f0.y * gv0.y + f0.z * gv0.z + f0.w * gv0.w
                        + f1.x * gv1.x + f1.y * gv1.y + f1.z * gv1.z + f1.w * gv1.w;
                float p = __expf(s);
                if (diag && nloc < mloc) p = 0.f;
                pv[i] = p;
            }
            *(float4*)&Pt[nloc * 68 + mg0]     = make_float4(pv[0], pv[1], pv[2], pv[3]);
            *(float4*)&Pt[nloc * 68 + mg0 + 4] = make_float4(pv[4], pv[5], pv[6], pv[7]);
        }
        __syncthreads();

        // Phase 2: acc[m][c] += sum_n P[n][m] * V'[n][c]  (8x4 per thread)
        #pragma unroll 4
        for (int nn = 0; nn < 64; nn++) {
            float4 p0 = *(float4*)&Pt[nn * 68 + tm];
            float4 p1 = *(float4*)&Pt[nn * 68 + tm + 4];
            float4 vv = *(float4*)&Vt[nn * 68 + tc];
            acc[0][0] += p0.x * vv.x; acc[0][1] += p0.x * vv.y;
            acc[0][2] += p0.x * vv.z; acc[0][3] += p0.x * vv.w;
            acc[1][0] += p0.y * vv.x; acc[1][1] += p0.y * vv.y;
            acc[1][2] += p0.y * vv.z; acc[1][3] += p0.y * vv.w;
            acc[2][0] += p0.z * vv.x; acc[2][1] += p0.z * vv.y;
            acc[2][2] += p0.z * vv.z; acc[2][3] += p0.z * vv.w;
            acc[3][0] += p0.w * vv.x; acc[3][1] += p0.w * vv.y;
            acc[3][2] += p0.w * vv.z; acc[3][3] += p0.w * vv.w;
            acc[4][0] += p1.x * vv.x; acc[4][1] += p1.x * vv.y;
            acc[4][2] += p1.x * vv.z; acc[4][3] += p1.x * vv.w;
            acc[5][0] += p1.y * vv.x; acc[5][1] += p1.y * vv.y;
            acc[5][2] += p1.y * vv.z; acc[5][3] += p1.y * vv.w;
            acc[6][0] += p1.z * vv.x; acc[6][1] += p1.z * vv.y;
            acc[6][2] += p1.z * vv.z; acc[6][3] += p1.z * vv.w;
            acc[7][0] += p1.w * vv.x; acc[7][1] += p1.w * vv.y;
            acc[7][2] += p1.w * vv.z; acc[7][3] += p1.w * vv.w;
        }
        __syncthreads();
    }

    #pragma unroll
    for (int i = 0; i < 8; i++)
        #pragma unroll
        for (int j = 0; j < 4; j++)
            atomicAdd(&g_O[((b * 64 + tc + j) << 12) + m_base + tm + i], acc[i][j]);
}

// ---------------------------------------------------------------------------
// Epilogue: y = gamma * O + x.  1,048,576 floats = 262,144 float4
//  -> grid 1024 x 256 threads.
// ---------------------------------------------------------------------------
__global__ __launch_bounds__(256) void kE(
    const float* __restrict__ x,
    const float* __restrict__ gamma,
    float* __restrict__ out)
{
    const float gm = gamma[0];
    int i = blockIdx.x * 256 + threadIdx.x;
    float4 o  = ((const float4*)g_O)[i];
    float4 xv = ((const float4*)x)[i];
    ((float4*)out)[i] = make_float4(gm * o.x + xv.x, gm * o.y + xv.y,
                                    gm * o.z + xv.z, gm * o.w + xv.w);
}

// ---------------------------------------------------------------------------
extern "C" void kernel_launch(void* const* d_in, const int* in_sizes, int n_in,
                              void* d_out, int out_size)
{
    const float* x     = (const float*)d_in[0];
    const float* Wf    = (const float*)d_in[1];
    const float* bf    = (const float*)d_in[2];
    const float* Wg    = (const float*)d_in[3];
    const float* bg    = (const float*)d_in[4];
    const float* Wh    = (const float*)d_in[5];
    const float* bh    = (const float*)d_in[6];
    const float* gamma = (const float*)d_in[7];
    float* out = (float*)d_out;

    kZ<<<1024, 256>>>();
    kA<<<dim3(32, 4), 256>>>(x, Wf, bf, Wg, bg, Wh, bh);
    kB1<<<dim3(8, 4, 4), 256>>>();
    kB2<<<64, 256>>>();
    kC<<<640, 128>>>();
    kE<<<1024, 256>>>(x, gamma, out);
}

// round 6
// speedup vs baseline: 2.4394x; 1.6751x over previous
#include <cuda_runtime.h>
#include <cuda_bf16.h>

#define HW   4096
#define CCH  64
#define BB   4
#define KK   8
#define PTS  72   // Pt row stride in bf16 (144B, 16B-aligned, conflict-free ldmatrix)
#define VTS  72

// Scratch (allocation-free rule: __device__ globals)
__device__ float g_f[BB * HW * KK];      // [b][n][k]
__device__ float g_g[BB * HW * KK];      // [b][n][k]
__device__ float g_h[BB * CCH * HW];     // [b][c][n]
__device__ float g_part[BB * 4 * HW];    // partial denom sums
__device__ float g_rden[BB * HW];        // 1/denom
__device__ float g_O[BB * CCH * HW];     // attention output accumulator

// ---------------------------------------------------------------------------
__global__ __launch_bounds__(256) void kZ()
{
    ((float4*)g_O)[blockIdx.x * 256 + threadIdx.x] = make_float4(0.f, 0.f, 0.f, 0.f);
}

// ---------------------------------------------------------------------------
// Kernel A: f = Wf@x+bf, g = Wg@x+bg, h = Wh@x+bh (1x1 convs)
// ---------------------------------------------------------------------------
__global__ __launch_bounds__(256) void kA(
    const float* __restrict__ x,
    const float* __restrict__ Wf, const float* __restrict__ bf,
    const float* __restrict__ Wg, const float* __restrict__ bg,
    const float* __restrict__ Wh, const float* __restrict__ bh)
{
    __shared__ float xs[64 * 128];
    const int t  = threadIdx.x;
    const int b  = blockIdx.y;
    const int n0 = blockIdx.x * 128;

    #pragma unroll
    for (int r = 0; r < 32; r++) {
        int lin = r * 256 + t;
        int c = lin >> 7, nn = lin & 127;
        xs[lin] = x[((b * 64 + c) << 12) + n0 + nn];
    }
    __syncthreads();

    const int n = t & 127, half = t >> 7;
    const int rowbase = half * 32;
    const float* Wfg = half ? Wg : Wf;
    const float* bfg = half ? bg : bf;

    float acch[32], accfg[8];
    #pragma unroll
    for (int o = 0; o < 32; o++) acch[o] = bh[rowbase + o];
    #pragma unroll
    for (int k = 0; k < 8; k++)  accfg[k] = bfg[k];

    #pragma unroll
    for (int c0 = 0; c0 < 64; c0 += 8) {
        float xv[8];
        #pragma unroll
        for (int j = 0; j < 8; j++) xv[j] = xs[(c0 + j) * 128 + n];

        #pragma unroll
        for (int o = 0; o < 32; o++) {
            const float4* w = (const float4*)(Wh + (rowbase + o) * 64 + c0);
            float4 w0 = w[0], w1 = w[1];
            acch[o] += w0.x * xv[0] + w0.y * xv[1] + w0.z * xv[2] + w0.w * xv[3]
                     + w1.x * xv[4] + w1.y * xv[5] + w1.z * xv[6] + w1.w * xv[7];
        }
        #pragma unroll
        for (int k = 0; k < 8; k++) {
            const float4* w = (const float4*)(Wfg + k * 64 + c0);
            float4 w0 = w[0], w1 = w[1];
            accfg[k] += w0.x * xv[0] + w0.y * xv[1] + w0.z * xv[2] + w0.w * xv[3]
                      + w1.x * xv[4] + w1.y * xv[5] + w1.z * xv[6] + w1.w * xv[7];
        }
    }

    const int ng = n0 + n;
    #pragma unroll
    for (int o = 0; o < 32; o++)
        g_h[((b * 64 + rowbase + o) << 12) + ng] = acch[o];

    float* dst = (half ? g_g : g_f) + (b * HW + ng) * 8;
    *(float4*)(dst)     = make_float4(accfg[0], accfg[1], accfg[2], accfg[3]);
    *(float4*)(dst + 4) = make_float4(accfg[4], accfg[5], accfg[6], accfg[7]);
}

// ---------------------------------------------------------------------------
// Kernel B1: partial denominators.
// ---------------------------------------------------------------------------
__global__ __launch_bounds__(256) void kB1()
{
    __shared__ float fs[128 * 8];
    const int t  = threadIdx.x;
    const int b  = blockIdx.z;
    const int mq = blockIdx.y;
    const int na = blockIdx.x * 256 + t;
    const int nb = na + 2048;

    const float4* gpa = (const float4*)&g_g[(b * HW + na) * 8];
    const float4 ga0 = gpa[0], ga1 = gpa[1];
    const float4* gpb = (const float4*)&g_g[(b * HW + nb) * 8];
    const float4 gb0 = gpb[0], gb1 = gpb[1];

    float acca = 0.f, accb = 0.f;
    const int mend = mq * 1024 + 1024;
    for (int m0 = mq * 1024; m0 < mend; m0 += 128) {
        ((float4*)fs)[t] = ((const float4*)&g_f[(b * HW + m0) * 8])[t];
        __syncthreads();
        #pragma unroll 8
        for (int mm = 0; mm < 128; mm++) {
            float4 f0 = *(float4*)&fs[mm * 8];
            float4 f1 = *(float4*)&fs[mm * 8 + 4];
            float sa = f0.x * ga0.x + f0.y * ga0.y + f0.z * ga0.z + f0.w * ga0.w
                     + f1.x * ga1.x + f1.y * ga1.y + f1.z * ga1.z + f1.w * ga1.w;
            float sb = f0.x * gb0.x + f0.y * gb0.y + f0.z * gb0.z + f0.w * gb0.w
                     + f1.x * gb1.x + f1.y * gb1.y + f1.z * gb1.z + f1.w * gb1.w;
            acca += __expf(sa);
            accb += __expf(sb);
        }
        __syncthreads();
    }
    g_part[(b * 4 + mq) * HW + na] = acca;
    g_part[(b * 4 + mq) * HW + nb] = accb;
}

__global__ __launch_bounds__(256) void kB2()
{
    int i = blockIdx.x * 256 + threadIdx.x;
    int b = i >> 12, n = i & 4095;
    float s = g_part[(b * 4 + 0) * HW + n] + g_part[(b * 4 + 1) * HW + n]
            + g_part[(b * 4 + 2) * HW + n] + g_part[(b * 4 + 3) * HW + n];
    g_rden[i] = 1.0f / s;
}

// ---------------------------------------------------------------------------
// Kernel C: masked attention GEMM with bf16 mma.sync.
// Output tile 128m x 64c per block, 256 threads (8 warps, 16m x 64c each).
// Tasks: (b, mt in [0,32)), n-tiles of 64 from the diagonal, chunks of 16.
// chunks(mt) = ceil((64-2mt)/16); 80 tasks/b -> 320 blocks. Atomic reduce.
// ---------------------------------------------------------------------------
__global__ __launch_bounds__(256) void kC()
{
    __shared__ float fs[128 * 8];
    __shared__ float gs[64 * 8];
    __shared__ __nv_bfloat16 Pt[128 * PTS];   // [m][n] bf16 (A, row-major)
    __shared__ __nv_bfloat16 Vt[64 * VTS];    // [n][c] bf16 (B, k-major)

    const int tid = threadIdx.x;
    const int bid = blockIdx.x;
    const int b = bid & 3;
    int t = bid >> 2;                          // 0..79

    int mt = 0;
    for (;;) {
        int ch = (64 - 2 * mt + 15) >> 4;
        if (t < ch) break;
        t -= ch; mt++;
    }
    const int m_base = mt * 128;
    const int nt_begin = 2 * mt + t * 16;
    const int nt_end = (nt_begin + 16 < 64) ? nt_begin + 16 : 64;

    // f tile [128 m][8] = 256 float4
    ((float4*)fs)[tid] = ((const float4*)&g_f[(b * HW + m_base) * 8])[tid];

    const int wid  = tid >> 5, lane = tid & 31;
    const int wm   = wid * 16;                 // warp's m rows
    const int ng0  = tid & 15;                 // phase-1 n lane
    const int mg0  = (tid >> 4) * 8;           // phase-1 m base

    float acc[8][4];
    #pragma unroll
    for (int i = 0; i < 8; i++)
        #pragma unroll
        for (int j = 0; j < 4; j++) acc[i][j] = 0.f;

    // ldmatrix smem addresses (lane-dependent parts precomputed)
    const unsigned ptS = (unsigned)__cvta_generic_to_shared(Pt);
    const unsigned vtS = (unsigned)__cvta_generic_to_shared(Vt);
    const int lrow = lane & 15, lcol = (lane >> 4) * 8;
    const unsigned aBase = ptS + ((wm + lrow) * PTS + lcol) * 2;   // + k*32
    const unsigned bBase = vtS + (lrow * VTS + lcol) * 2;          // + k*16*VTS*2 + c16*32

    for (int nt = nt_begin; nt < nt_end; nt++) {
        const int n0 = nt * 64;
        if (tid < 128)
            ((float4*)gs)[tid] = ((const float4*)&g_g[(b * HW + n0) * 8])[tid];

        // Vt[n][c] = bf16( h[b][c][n0+n] * rden[n0+n] )
        #pragma unroll
        for (int r = 0; r < 16; r++) {
            int lin = r * 256 + tid;
            int c = lin >> 6, nn = lin & 63;
            Vt[nn * VTS + c] = __float2bfloat16(
                g_h[((b * 64 + c) << 12) + n0 + nn] * g_rden[b * HW + n0 + nn]);
        }
        __syncthreads();

        // Phase 1: Pt[m][n] = bf16(exp(f_m . g_n)), masked to n_glob >= m_glob
        const int off = n0 - m_base;           // >=128 -> never masked
        #pragma unroll
        for (int j = 0; j < 4; j++) {
            const int nloc = ng0 + 16 * j;
            float4 gv0 = *(float4*)&gs[nloc * 8];
            float4 gv1 = *(float4*)&gs[nloc * 8 + 4];
            #pragma unroll
            for (int i = 0; i < 8; i++) {
                const int mloc = mg0 + i;
                float4 f0 = *(float4*)&fs[mloc * 8];
                float4 f1 = *(float4*)&fs[mloc * 8 + 4];
                float s = f0.x * gv0.x + f0.y * gv0.y + f0.z * gv0.z + f0.w * gv0.w
                        + f1.x * gv1.x + f1.y * gv1.y + f1.z * gv1.z + f1.w * gv1.w;
                float p = __expf(s);
                if (nloc + off < mloc) p = 0.f;
                Pt[mloc * PTS + nloc] = __float2bfloat16(p);
            }
        }
        __syncthreads();

        // Phase 2: acc += Pt[wm..wm+16][0..64] @ Vt[0..64][0..64] via HMMA
        #pragma unroll
        for (int k = 0; k < 4; k++) {
            unsigned a0, a1, a2, a3;
            asm volatile("ldmatrix.sync.aligned.m8n8.x4.shared.b16 {%0,%1,%2,%3}, [%4];"
                         : "=r"(a0), "=r"(a1), "=r"(a2), "=r"(a3)
                         : "r"(aBase + k * 32));
            #pragma unroll
            for (int cc = 0; cc < 4; cc++) {
                unsigned b0, b1, b2, b3;
                asm volatile("ldmatrix.sync.aligned.m8n8.x4.trans.shared.b16 {%0,%1,%2,%3}, [%4];"
                             : "=r"(b0), "=r"(b1), "=r"(b2), "=r"(b3)
                             : "r"(bBase + k * 16 * VTS * 2 + cc * 32));
                float* d0 = acc[cc * 2];
                asm volatile("mma.sync.aligned.m16n8k16.row.col.f32.bf16.bf16.f32 "
                             "{%0,%1,%2,%3}, {%4,%5,%6,%7}, {%8,%9}, {%0,%1,%2,%3};"
                             : "+f"(d0[0]), "+f"(d0[1]), "+f"(d0[2]), "+f"(d0[3])
                             : "r"(a0), "r"(a1), "r"(a2), "r"(a3), "r"(b0), "r"(b1));
                float* d1 = acc[cc * 2 + 1];
                asm volatile("mma.sync.aligned.m16n8k16.row.col.f32.bf16.bf16.f32 "
                             "{%0,%1,%2,%3}, {%4,%5,%6,%7}, {%8,%9}, {%0,%1,%2,%3};"
                             : "+f"(d1[0]), "+f"(d1[1]), "+f"(d1[2]), "+f"(d1[3])
                             : "r"(a0), "r"(a1), "r"(a2), "r"(a3), "r"(b2), "r"(b3));
            }
        }
        __syncthreads();
    }

    // Epilogue: fragment -> atomic accumulate into g_O[b][c][m]
    const int fr = lane >> 2, fc = (lane & 3) * 2;
    const int m0g = m_base + wm + fr;
    #pragma unroll
    for (int q = 0; q < 8; q++) {
        int c = q * 8 + fc;
        atomicAdd(&g_O[((b * 64 + c    ) << 12) + m0g    ], acc[q][0]);
        atomicAdd(&g_O[((b * 64 + c + 1) << 12) + m0g    ], acc[q][1]);
        atomicAdd(&g_O[((b * 64 + c    ) << 12) + m0g + 8], acc[q][2]);
        atomicAdd(&g_O[((b * 64 + c + 1) << 12) + m0g + 8], acc[q][3]);
    }
}

// ---------------------------------------------------------------------------
__global__ __launch_bounds__(256) void kE(
    const float* __restrict__ x,
    const float* __restrict__ gamma,
    float* __restrict__ out)
{
    const float gm = gamma[0];
    int i = blockIdx.x * 256 + threadIdx.x;
    float4 o  = ((const float4*)g_O)[i];
    float4 xv = ((const float4*)x)[i];
    ((float4*)out)[i] = make_float4(gm * o.x + xv.x, gm * o.y + xv.y,
                                    gm * o.z + xv.z, gm * o.w + xv.w);
}

// ---------------------------------------------------------------------------
extern "C" void kernel_launch(void* const* d_in, const int* in_sizes, int n_in,
                              void* d_out, int out_size)
{
    const float* x     = (const float*)d_in[0];
    const float* Wf    = (const float*)d_in[1];
    const float* bf    = (const float*)d_in[2];
    const float* Wg    = (const float*)d_in[3];
    const float* bg    = (const float*)d_in[4];
    const float* Wh    = (const float*)d_in[5];
    const float* bh    = (const float*)d_in[6];
    const float* gamma = (const float*)d_in[7];
    float* out = (float*)d_out;

    kZ<<<1024, 256>>>();
    kA<<<dim3(32, 4), 256>>>(x, Wf, bf, Wg, bg, Wh, bh);
    kB1<<<dim3(8, 4, 4), 256>>>();
    kB2<<<64, 256>>>();
    kC<<<320, 256>>>();
    kE<<<1024, 256>>>(x, gamma, out);
}

// round 7
// speedup vs baseline: 2.4571x; 1.0072x over previous
#include <cuda_runtime.h>
#include <cuda_bf16.h>

#define HW   4096
#define CCH  64
#define BB   4
#define KK   8
#define PTS  72   // Pt row stride in bf16 (144B, 16B-aligned, conflict-free ldmatrix)
#define VTS  72

// Scratch (allocation-free rule: __device__ globals)
__device__ float g_f[BB * HW * KK];      // [b][n][k]
__device__ float g_g[BB * HW * KK];      // [b][n][k]
__device__ float g_h[BB * CCH * HW];     // [b][c][n]
__device__ float g_part[BB * 4 * HW];    // partial denom sums
__device__ float g_rden[BB * HW];        // 1/denom
__device__ float g_O[BB * CCH * HW];     // attention output accumulator

// ---------------------------------------------------------------------------
__global__ __launch_bounds__(256) void kZ()
{
    ((float4*)g_O)[blockIdx.x * 256 + threadIdx.x] = make_float4(0.f, 0.f, 0.f, 0.f);
}

// ---------------------------------------------------------------------------
// Kernel A: f = Wf@x+bf, g = Wg@x+bg, h = Wh@x+bh (1x1 convs)
// ---------------------------------------------------------------------------
__global__ __launch_bounds__(256) void kA(
    const float* __restrict__ x,
    const float* __restrict__ Wf, const float* __restrict__ bf,
    const float* __restrict__ Wg, const float* __restrict__ bg,
    const float* __restrict__ Wh, const float* __restrict__ bh)
{
    __shared__ float xs[64 * 128];
    const int t  = threadIdx.x;
    const int b  = blockIdx.y;
    const int n0 = blockIdx.x * 128;

    #pragma unroll
    for (int r = 0; r < 32; r++) {
        int lin = r * 256 + t;
        int c = lin >> 7, nn = lin & 127;
        xs[lin] = x[((b * 64 + c) << 12) + n0 + nn];
    }
    __syncthreads();

    const int n = t & 127, half = t >> 7;
    const int rowbase = half * 32;
    const float* Wfg = half ? Wg : Wf;
    const float* bfg = half ? bg : bf;

    float acch[32], accfg[8];
    #pragma unroll
    for (int o = 0; o < 32; o++) acch[o] = bh[rowbase + o];
    #pragma unroll
    for (int k = 0; k < 8; k++)  accfg[k] = bfg[k];

    #pragma unroll
    for (int c0 = 0; c0 < 64; c0 += 8) {
        float xv[8];
        #pragma unroll
        for (int j = 0; j < 8; j++) xv[j] = xs[(c0 + j) * 128 + n];

        #pragma unroll
        for (int o = 0; o < 32; o++) {
            const float4* w = (const float4*)(Wh + (rowbase + o) * 64 + c0);
            float4 w0 = w[0], w1 = w[1];
            acch[o] += w0.x * xv[0] + w0.y * xv[1] + w0.z * xv[2] + w0.w * xv[3]
                     + w1.x * xv[4] + w1.y * xv[5] + w1.z * xv[6] + w1.w * xv[7];
        }
        #pragma unroll
        for (int k = 0; k < 8; k++) {
            const float4* w = (const float4*)(Wfg + k * 64 + c0);
            float4 w0 = w[0], w1 = w[1];
            accfg[k] += w0.x * xv[0] + w0.y * xv[1] + w0.z * xv[2] + w0.w * xv[3]
                      + w1.x * xv[4] + w1.y * xv[5] + w1.z * xv[6] + w1.w * xv[7];
        }
    }

    const int ng = n0 + n;
    #pragma unroll
    for (int o = 0; o < 32; o++)
        g_h[((b * 64 + rowbase + o) << 12) + ng] = acch[o];

    float* dst = (half ? g_g : g_f) + (b * HW + ng) * 8;
    *(float4*)(dst)     = make_float4(accfg[0], accfg[1], accfg[2], accfg[3]);
    *(float4*)(dst + 4) = make_float4(accfg[4], accfg[5], accfg[6], accfg[7]);
}

// ---------------------------------------------------------------------------
// Kernel B1: partial denominators.
// ---------------------------------------------------------------------------
__global__ __launch_bounds__(256) void kB1()
{
    __shared__ float fs[128 * 8];
    const int t  = threadIdx.x;
    const int b  = blockIdx.z;
    const int mq = blockIdx.y;
    const int na = blockIdx.x * 256 + t;
    const int nb = na + 2048;

    const float4* gpa = (const float4*)&g_g[(b * HW + na) * 8];
    const float4 ga0 = gpa[0], ga1 = gpa[1];
    const float4* gpb = (const float4*)&g_g[(b * HW + nb) * 8];
    const float4 gb0 = gpb[0], gb1 = gpb[1];

    float acca = 0.f, accb = 0.f;
    const int mend = mq * 1024 + 1024;
    for (int m0 = mq * 1024; m0 < mend; m0 += 128) {
        ((float4*)fs)[t] = ((const float4*)&g_f[(b * HW + m0) * 8])[t];
        __syncthreads();
        #pragma unroll 8
        for (int mm = 0; mm < 128; mm++) {
            float4 f0 = *(float4*)&fs[mm * 8];
            float4 f1 = *(float4*)&fs[mm * 8 + 4];
            float sa = f0.x * ga0.x + f0.y * ga0.y + f0.z * ga0.z + f0.w * ga0.w
                     + f1.x * ga1.x + f1.y * ga1.y + f1.z * ga1.z + f1.w * ga1.w;
            float sb = f0.x * gb0.x + f0.y * gb0.y + f0.z * gb0.z + f0.w * gb0.w
                     + f1.x * gb1.x + f1.y * gb1.y + f1.z * gb1.z + f1.w * gb1.w;
            acca += __expf(sa);
            accb += __expf(sb);
        }
        __syncthreads();
    }
    g_part[(b * 4 + mq) * HW + na] = acca;
    g_part[(b * 4 + mq) * HW + nb] = accb;
}

__global__ __launch_bounds__(256) void kB2()
{
    int i = blockIdx.x * 256 + threadIdx.x;
    int b = i >> 12, n = i & 4095;
    float s = g_part[(b * 4 + 0) * HW + n] + g_part[(b * 4 + 1) * HW + n]
            + g_part[(b * 4 + 2) * HW + n] + g_part[(b * 4 + 3) * HW + n];
    g_rden[i] = 1.0f / s;
}

// ---------------------------------------------------------------------------
// Kernel C: masked attention GEMM with bf16 mma.sync.
// Output tile 128m x 64c per block, 256 threads (8 warps, 16m x 64c each).
// Tasks: (b, mt in [0,32)), n-tiles of 64 from the diagonal, chunks of 16.
// chunks(mt) = ceil((64-2mt)/16); 80 tasks/b -> 320 blocks. Atomic reduce.
// ---------------------------------------------------------------------------
__global__ __launch_bounds__(256) void kC()
{
    __shared__ float fs[128 * 8];
    __shared__ float gs[64 * 8];
    __shared__ __nv_bfloat16 Pt[128 * PTS];   // [m][n] bf16 (A, row-major)
    __shared__ __nv_bfloat16 Vt[64 * VTS];    // [n][c] bf16 (B, k-major)

    const int tid = threadIdx.x;
    const int bid = blockIdx.x;
    const int b = bid & 3;
    int t = bid >> 2;                          // 0..79

    int mt = 0;
    for (;;) {
        int ch = (64 - 2 * mt + 15) >> 4;
        if (t < ch) break;
        t -= ch; mt++;
    }
    const int m_base = mt * 128;
    const int nt_begin = 2 * mt + t * 16;
    const int nt_end = (nt_begin + 16 < 64) ? nt_begin + 16 : 64;

    // f tile [128 m][8] = 256 float4
    ((float4*)fs)[tid] = ((const float4*)&g_f[(b * HW + m_base) * 8])[tid];

    const int wid  = tid >> 5, lane = tid & 31;
    const int wm   = wid * 16;                 // warp's m rows
    const int ng0  = tid & 15;                 // phase-1 n lane
    const int mg0  = (tid >> 4) * 8;           // phase-1 m base

    float acc[8][4];
    #pragma unroll
    for (int i = 0; i < 8; i++)
        #pragma unroll
        for (int j = 0; j < 4; j++) acc[i][j] = 0.f;

    // ldmatrix smem addresses (lane-dependent parts precomputed)
    const unsigned ptS = (unsigned)__cvta_generic_to_shared(Pt);
    const unsigned vtS = (unsigned)__cvta_generic_to_shared(Vt);
    const int lrow = lane & 15, lcol = (lane >> 4) * 8;
    const unsigned aBase = ptS + ((wm + lrow) * PTS + lcol) * 2;   // + k*32
    const unsigned bBase = vtS + (lrow * VTS + lcol) * 2;          // + k*16*VTS*2 + c16*32

    for (int nt = nt_begin; nt < nt_end; nt++) {
        const int n0 = nt * 64;
        if (tid < 128)
            ((float4*)gs)[tid] = ((const float4*)&g_g[(b * HW + n0) * 8])[tid];

        // Vt[n][c] = bf16( h[b][c][n0+n] * rden[n0+n] )
        #pragma unroll
        for (int r = 0; r < 16; r++) {
            int lin = r * 256 + tid;
            int c = lin >> 6, nn = lin & 63;
            Vt[nn * VTS + c] = __float2bfloat16(
                g_h[((b * 64 + c) << 12) + n0 + nn] * g_rden[b * HW + n0 + nn]);
        }
        __syncthreads();

        // Phase 1: Pt[m][n] = bf16(exp(f_m . g_n)), masked to n_glob >= m_glob
        const int off = n0 - m_base;           // >=128 -> never masked
        #pragma unroll
        for (int j = 0; j < 4; j++) {
            const int nloc = ng0 + 16 * j;
            float4 gv0 = *(float4*)&gs[nloc * 8];
            float4 gv1 = *(float4*)&gs[nloc * 8 + 4];
            #pragma unroll
            for (int i = 0; i < 8; i++) {
                const int mloc = mg0 + i;
                float4 f0 = *(float4*)&fs[mloc * 8];
                float4 f1 = *(float4*)&fs[mloc * 8 + 4];
                float s = f0.x * gv0.x + f0.y * gv0.y + f0.z * gv0.z + f0.w * gv0.w
                        + f1.x * gv1.x + f1.y * gv1.y + f1.z * gv1.z + f1.w * gv1.w;
                float p = __expf(s);
                if (nloc + off < mloc) p = 0.f;
                Pt[mloc * PTS + nloc] = __float2bfloat16(p);
            }
        }
        __syncthreads();

        // Phase 2: acc += Pt[wm..wm+16][0..64] @ Vt[0..64][0..64] via HMMA
        #pragma unroll
        for (int k = 0; k < 4; k++) {
            unsigned a0, a1, a2, a3;
            asm volatile("ldmatrix.sync.aligned.m8n8.x4.shared.b16 {%0,%1,%2,%3}, [%4];"
                         : "=r"(a0), "=r"(a1), "=r"(a2), "=r"(a3)
                         : "r"(aBase + k * 32));
            #pragma unroll
            for (int cc = 0; cc < 4; cc++) {
                unsigned b0, b1, b2, b3;
                asm volatile("ldmatrix.sync.aligned.m8n8.x4.trans.shared.b16 {%0,%1,%2,%3}, [%4];"
                             : "=r"(b0), "=r"(b1), "=r"(b2), "=r"(b3)
                             : "r"(bBase + k * 16 * VTS * 2 + cc * 32));
                float* d0 = acc[cc * 2];
                asm volatile("mma.sync.aligned.m16n8k16.row.col.f32.bf16.bf16.f32 "
                             "{%0,%1,%2,%3}, {%4,%5,%6,%7}, {%8,%9}, {%0,%1,%2,%3};"
                             : "+f"(d0[0]), "+f"(d0[1]), "+f"(d0[2]), "+f"(d0[3])
                             : "r"(a0), "r"(a1), "r"(a2), "r"(a3), "r"(b0), "r"(b1));
                float* d1 = acc[cc * 2 + 1];
                asm volatile("mma.sync.aligned.m16n8k16.row.col.f32.bf16.bf16.f32 "
                             "{%0,%1,%2,%3}, {%4,%5,%6,%7}, {%8,%9}, {%0,%1,%2,%3};"
                             : "+f"(d1[0]), "+f"(d1[1]), "+f"(d1[2]), "+f"(d1[3])
                             : "r"(a0), "r"(a1), "r"(a2), "r"(a3), "r"(b2), "r"(b3));
            }
        }
        __syncthreads();
    }

    // Epilogue: fragment -> atomic accumulate into g_O[b][c][m]
    const int fr = lane >> 2, fc = (lane & 3) * 2;
    const int m0g = m_base + wm + fr;
    #pragma unroll
    for (int q = 0; q < 8; q++) {
        int c = q * 8 + fc;
        atomicAdd(&g_O[((b * 64 + c    ) << 12) + m0g    ], acc[q][0]);
        atomicAdd(&g_O[((b * 64 + c + 1) << 12) + m0g    ], acc[q][1]);
        atomicAdd(&g_O[((b * 64 + c    ) << 12) + m0g + 8], acc[q][2]);
        atomicAdd(&g_O[((b * 64 + c + 1) << 12) + m0g + 8], acc[q][3]);
    }
}

// ---------------------------------------------------------------------------
__global__ __launch_bounds__(256) void kE(
    const float* __restrict__ x,
    const float* __restrict__ gamma,
    float* __restrict__ out)
{
    const float gm = gamma[0];
    int i = blockIdx.x * 256 + threadIdx.x;
    float4 o  = ((const float4*)g_O)[i];
    float4 xv = ((const float4*)x)[i];
    ((float4*)out)[i] = make_float4(gm * o.x + xv.x, gm * o.y + xv.y,
                                    gm * o.z + xv.z, gm * o.w + xv.w);
}

// ---------------------------------------------------------------------------
extern "C" void kernel_launch(void* const* d_in, const int* in_sizes, int n_in,
                              void* d_out, int out_size)
{
    const float* x     = (const float*)d_in[0];
    const float* Wf    = (const float*)d_in[1];
    const float* bf    = (const float*)d_in[2];
    const float* Wg    = (const float*)d_in[3];
    const float* bg    = (const float*)d_in[4];
    const float* Wh    = (const float*)d_in[5];
    const float* bh    = (const float*)d_in[6];
    const float* gamma = (const float*)d_in[7];
    float* out = (float*)d_out;

    kZ<<<1024, 256>>>();
    kA<<<dim3(32, 4), 256>>>(x, Wf, bf, Wg, bg, Wh, bh);
    kB1<<<dim3(8, 4, 4), 256>>>();
    kB2<<<64, 256>>>();
    kC<<<320, 256>>>();
    kE<<<1024, 256>>>(x, gamma, out);
}